// round 12
// baseline (speedup 1.0000x reference)
#include <cuda_runtime.h>
#include <cuda_bf16.h>
#include <math.h>
#include <stdint.h>

// TopKRouter: 3-pass BF16 split GEMM, barrier-free mainloop.
// A fragments: direct LDG.64 from x + in-register bf16 hi/lo split.
// B fragments: pre-packed in mma lane order (L2-resident), direct LDG.128.
// Warp K-split (k = 16*wid + 64*j), partials reduced in smem at epilogue.
// fp64 rescue for near-tied top-2. N=16384, D=2048, E=64.
// Output: [0,2N) weights | [2N,4N) idx (float) | [4N,68N) logits

#define DMODEL   2048
#define NEXP     64
#define BM       64
#define NITER    32                  // k16-slices per warp (4 warps x 32 x 16 = 2048)
#define NTHREADS 128
#define LPITCH   65
#define THR      5e-4f
#define SMEM_BYTES (4 * 64 * LPITCH * 4)   // 66560: 4 warp-partial tiles

// B fragments: [slice 0..127][p 0..3][lane 0..31] uint4
//   uint4 = (b0,b1 for nt=2p) , (b0,b1 for nt=2p+1)
__device__ uint4 g_bfh[128 * 4 * 32];
__device__ uint4 g_bfl[128 * 4 * 32];

#define MMAB(c, a0, a1, a2, a3, b0, b1) asm volatile(                     \
    "mma.sync.aligned.m16n8k16.row.col.f32.bf16.bf16.f32 "                \
    "{%0,%1,%2,%3}, {%4,%5,%6,%7}, {%8,%9}, {%0,%1,%2,%3};"               \
    : "+f"((c)[0]), "+f"((c)[1]), "+f"((c)[2]), "+f"((c)[3])              \
    : "r"(a0), "r"(a1), "r"(a2), "r"(a3), "r"(b0), "r"(b1))

// pack 2 floats (f0 = even k, f1 = odd k) -> bf16x2 hi + bf16x2 lo residual
static __device__ __forceinline__ void split2(float f0, float f1,
                                              uint32_t& h, uint32_t& l) {
    asm("cvt.rn.bf16x2.f32 %0, %1, %2;" : "=r"(h) : "f"(f1), "f"(f0));
    float b0 = __uint_as_float(h << 16);
    float b1 = __uint_as_float(h & 0xffff0000u);
    asm("cvt.rn.bf16x2.f32 %0, %1, %2;" : "=r"(l) : "f"(f1 - b1), "f"(f0 - b0));
}

// ---- pre-kernel: pack W into mma-fragment order, bf16 hi/lo ----
__global__ void wfrag_kernel(const float* __restrict__ Wg) {
    const int idx  = blockIdx.x * 256 + threadIdx.x;   // 16384 threads
    const int lane = idx & 31;
    const int p    = (idx >> 5) & 3;
    const int s    = idx >> 7;          // k16 slice 0..127
    const int g    = lane >> 2;
    const int t    = lane & 3;
    const int k    = s * 16 + 2 * t;
    const float* wa = Wg + (size_t)(p * 16 + g)     * DMODEL;  // nt = 2p
    const float* wb = Wg + (size_t)(p * 16 + 8 + g) * DMODEL;  // nt = 2p+1
    uint4 h, l;
    split2(wa[k],     wa[k + 1], h.x, l.x);
    split2(wa[k + 8], wa[k + 9], h.y, l.y);
    split2(wb[k],     wb[k + 1], h.z, l.z);
    split2(wb[k + 8], wb[k + 9], h.w, l.w);
    g_bfh[(s * 4 + p) * 32 + lane] = h;
    g_bfl[(s * 4 + p) * 32 + lane] = l;
}

__global__ __launch_bounds__(NTHREADS, 2)
void router_mma_kernel(const float* __restrict__ x, const float* __restrict__ Wg,
                       float* __restrict__ w_out, float* __restrict__ i_out,
                       float* __restrict__ l_out)
{
    extern __shared__ __align__(16) float sm[];

    const int tid = threadIdx.x;
    const int wid = tid >> 5;      // warp = k16 sub-slice 0..3
    const int lid = tid & 31;
    const int g   = lid >> 2;
    const int t   = lid & 3;
    const int t0  = blockIdx.x * BM;

    float c[4][8][4];              // [mt][nt][reg] full 64x64 K-partial
    #pragma unroll
    for (int i = 0; i < 4; i++)
        #pragma unroll
        for (int j = 0; j < 8; j++)
            #pragma unroll
            for (int k = 0; k < 4; k++) c[i][j][k] = 0.0f;

    // A base: row (t0 + g), col 2t. Fragment offsets: +16*D per mt, +8*D row-hi,
    // +8 col-hi.
    const float* xb = x + (size_t)(t0 + g) * DMODEL + 2 * t;

    // prologue: load A raw for j=0 (k0 = 16*wid)
    float2 araw[4][4];
    {
        const int k0 = 16 * wid;
        #pragma unroll
        for (int mt = 0; mt < 4; mt++) {
            const float* r = xb + (size_t)mt * 16 * DMODEL + k0;
            araw[mt][0] = *(const float2*)(r);
            araw[mt][1] = *(const float2*)(r + 8 * DMODEL);
            araw[mt][2] = *(const float2*)(r + 8);
            araw[mt][3] = *(const float2*)(r + 8 * DMODEL + 8);
        }
    }

    #pragma unroll 1
    for (int j = 0; j < NITER; j++) {
        const int s = wid + 4 * j;

        // ---- B fragments: 8 coalesced LDG.128 (L2-hot) ----
        const uint4* bph = g_bfh + (size_t)s * 128 + lid;
        const uint4* bpl = g_bfl + (size_t)s * 128 + lid;
        uint4 BH[4], BL[4];
        #pragma unroll
        for (int p = 0; p < 4; p++) { BH[p] = bph[p * 32]; BL[p] = bpl[p * 32]; }

        const int k0n = 16 * wid + 64 * (j + 1);

        #pragma unroll
        for (int mt = 0; mt < 4; mt++) {
            // convert current A raw -> hi/lo fragments
            uint32_t ah[4], al[4];
            #pragma unroll
            for (int q = 0; q < 4; q++)
                split2(araw[mt][q].x, araw[mt][q].y, ah[q], al[q]);

            // prefetch next iteration's A raw (overlaps the MMAs below)
            if (j + 1 < NITER) {
                const float* r = xb + (size_t)mt * 16 * DMODEL + k0n;
                araw[mt][0] = *(const float2*)(r);
                araw[mt][1] = *(const float2*)(r + 8 * DMODEL);
                araw[mt][2] = *(const float2*)(r + 8);
                araw[mt][3] = *(const float2*)(r + 8 * DMODEL + 8);
            }

            // 24 MMAs: hh, hl, lh (dep distance 8 per accumulator)
            #pragma unroll
            for (int nt = 0; nt < 8; nt++) {
                const uint4& B = BH[nt >> 1];
                MMAB(c[mt][nt], ah[0], ah[1], ah[2], ah[3],
                     (nt & 1) ? B.z : B.x, (nt & 1) ? B.w : B.y);
            }
            #pragma unroll
            for (int nt = 0; nt < 8; nt++) {
                const uint4& B = BL[nt >> 1];
                MMAB(c[mt][nt], ah[0], ah[1], ah[2], ah[3],
                     (nt & 1) ? B.z : B.x, (nt & 1) ? B.w : B.y);
            }
            #pragma unroll
            for (int nt = 0; nt < 8; nt++) {
                const uint4& B = BH[nt >> 1];
                MMAB(c[mt][nt], al[0], al[1], al[2], al[3],
                     (nt & 1) ? B.z : B.x, (nt & 1) ? B.w : B.y);
            }
        }
    }

    // ---- epilogue: warp partials -> smem, reduce, decide ----
    {
        float* Pw = sm + wid * (64 * LPITCH);
        #pragma unroll
        for (int mt = 0; mt < 4; mt++) {
            const int row = 16 * mt + g;
            #pragma unroll
            for (int nt = 0; nt < 8; nt++) {
                const int col = 8 * nt + 2 * t;
                Pw[row * LPITCH + col]           = c[mt][nt][0];
                Pw[row * LPITCH + col + 1]       = c[mt][nt][1];
                Pw[(row + 8) * LPITCH + col]     = c[mt][nt][2];
                Pw[(row + 8) * LPITCH + col + 1] = c[mt][nt][3];
            }
        }
    }
    __syncthreads();

    float* L = sm;
    #pragma unroll
    for (int j = 0; j < 32; j++) {
        int idx = tid + 128 * j;
        int addr = (idx >> 6) * LPITCH + (idx & 63);
        L[addr] = (L[addr] + sm[64 * LPITCH + addr])
                + (sm[128 * LPITCH + addr] + sm[192 * LPITCH + addr]);
    }
    __syncthreads();

    // ---- per-token top-4 + near-tie fp64 rescue + softmax (warps 0,1) ----
    if (tid < BM) {
        const float* row = &L[tid * LPITCH];
        float v1 = -INFINITY, v2 = -INFINITY, v3 = -INFINITY, v4 = -INFINITY;
        int   i1 = 0, i2 = 0, i3 = 0, i4 = 0;
        #pragma unroll 8
        for (int e = 0; e < NEXP; e++) {
            float v = row[e];
            if (v > v1)      { v4=v3;i4=i3; v3=v2;i3=i2; v2=v1;i2=i1; v1=v;i1=e; }
            else if (v > v2) { v4=v3;i4=i3; v3=v2;i3=i2; v2=v;i2=e; }
            else if (v > v3) { v4=v3;i4=i3; v3=v;i3=e; }
            else if (v > v4) { v4=v;i4=e; }
        }

        const bool flagged = (v1 - v2 < THR) || (v2 - v3 < THR);
        unsigned m = __ballot_sync(0xffffffffu, flagged);
        while (m) {
            const int src = __ffs(m) - 1;
            m &= m - 1;
            const int tok = t0 + (tid & ~31) + src;
            int cand[4];
            cand[0] = __shfl_sync(0xffffffffu, i1, src);
            cand[1] = __shfl_sync(0xffffffffu, i2, src);
            cand[2] = __shfl_sync(0xffffffffu, i3, src);
            cand[3] = __shfl_sync(0xffffffffu, i4, src);

            const int slot = lid >> 3;
            const int kl   = lid & 7;
            const int e    = cand[slot];
            const float* xp = x  + (size_t)tok * DMODEL;
            const float* wp = Wg + (size_t)e   * DMODEL;

            double a0 = 0.0, a1 = 0.0, a2 = 0.0, a3 = 0.0;
            #pragma unroll 4
            for (int jj = 0; jj < 256; jj += 4) {
                int k0 = (jj + 0) * 8 + kl;
                int k1 = (jj + 1) * 8 + kl;
                int k2 = (jj + 2) * 8 + kl;
                int k3 = (jj + 3) * 8 + kl;
                a0 = fma((double)xp[k0], (double)wp[k0], a0);
                a1 = fma((double)xp[k1], (double)wp[k1], a1);
                a2 = fma((double)xp[k2], (double)wp[k2], a2);
                a3 = fma((double)xp[k3], (double)wp[k3], a3);
            }
            double tot = (a0 + a1) + (a2 + a3);
            tot += __shfl_xor_sync(0xffffffffu, tot, 4);
            tot += __shfl_xor_sync(0xffffffffu, tot, 2);
            tot += __shfl_xor_sync(0xffffffffu, tot, 1);

            double gv[4];
            gv[0] = __shfl_sync(0xffffffffu, tot, 0);
            gv[1] = __shfl_sync(0xffffffffu, tot, 8);
            gv[2] = __shfl_sync(0xffffffffu, tot, 16);
            gv[3] = __shfl_sync(0xffffffffu, tot, 24);

            if (lid == src) {
                int o1 = 0;
                #pragma unroll
                for (int s2 = 1; s2 < 4; s2++)
                    if (gv[s2] > gv[o1] || (gv[s2] == gv[o1] && cand[s2] < cand[o1])) o1 = s2;
                int o2 = (o1 == 0) ? 1 : 0;
                #pragma unroll
                for (int s2 = 0; s2 < 4; s2++) {
                    if (s2 == o1 || s2 == o2) continue;
                    if (gv[s2] > gv[o2] || (gv[s2] == gv[o2] && cand[s2] < cand[o2])) o2 = s2;
                }
                i1 = cand[o1]; i2 = cand[o2];
                v1 = row[i1];  v2 = row[i2];
            }
        }

        float S = 0.0f;
        #pragma unroll 8
        for (int e = 0; e < NEXP; e++) S += expf(row[e] - v1);
        const float p1  = expf(row[i1] - v1) / S;
        const float p2  = expf(v2 - v1) / S;
        const float inv = 1.0f / (p1 + p2 + 1e-10f);
        const size_t n = (size_t)(t0 + tid);
        w_out[2 * n]     = p1 * inv;
        w_out[2 * n + 1] = p2 * inv;
        i_out[2 * n]     = (float)i1;
        i_out[2 * n + 1] = (float)i2;
    }

    // coalesced logits store
    #pragma unroll
    for (int p = 0; p < 8; p++) {
        int id = tid + 128 * p;
        int rr = id >> 4, q = id & 15;
        float4 v;
        v.x = L[rr * LPITCH + 4 * q];
        v.y = L[rr * LPITCH + 4 * q + 1];
        v.z = L[rr * LPITCH + 4 * q + 2];
        v.w = L[rr * LPITCH + 4 * q + 3];
        *(float4*)(l_out + (size_t)(t0 + rr) * NEXP + 4 * q) = v;
    }
}

extern "C" void kernel_launch(void* const* d_in, const int* in_sizes, int n_in,
                              void* d_out, int out_size)
{
    const float* x  = (const float*)d_in[0];
    const float* Wg = (const float*)d_in[1];
    const int N = in_sizes[0] / DMODEL;       // 16384

    float* out   = (float*)d_out;
    float* w_out = out;
    float* i_out = out + (size_t)N * 2;
    float* l_out = out + (size_t)N * 4;

    wfrag_kernel<<<64, 256>>>(Wg);

    cudaFuncSetAttribute(router_mma_kernel,
                         cudaFuncAttributeMaxDynamicSharedMemorySize, SMEM_BYTES);
    router_mma_kernel<<<N / BM, NTHREADS, SMEM_BYTES>>>(x, Wg, w_out, i_out, l_out);
}

// round 13
// speedup vs baseline: 1.0567x; 1.0567x over previous
#include <cuda_runtime.h>
#include <cuda_bf16.h>
#include <math.h>
#include <stdint.h>

// TopKRouter: 3-pass BF16 split GEMM; 256 thr/CTA, warp tile 32x32x(2 k16),
// 2 CTAs/SM -> 16 warps/SM (2x prior). Smem staging + ldmatrix (R9 scheme),
// cp.async prepacked W, fp64 rescue for near-tied top-2.
// N=16384, D=2048, E=64. Output: [0,2N) weights | [2N,4N) idx | [4N,68N) logits

#define DMODEL   2048
#define NEXP     64
#define BM       64
#define KC       64                  // floats per chunk
#define NCHUNK   (DMODEL / KC)       // 32
#define NTHREADS 256
#define LPITCH   65
#define THR      5e-4f

// staging tiles: 64 rows x 64 bf16 (128 B data), pitch 144 B (conflict-free)
#define P2    144
#define TILE2 (64 * P2)              // 9216 B
#define XH_T  0
#define XL_T  TILE2
#define WH_T  (2 * TILE2)
#define WL_T  (3 * TILE2)
#define SBUF  (4 * TILE2)            // 36864 B
#define SMEM_BYTES (2 * SBUF)        // 73728 B

// epilogue regions (floats), inside smem after mainloop finishes
#define PPITCH 33
#define PSZ    (32 * PPITCH)         // 1056 floats per partial tile
#define L_OFF  (8 * PSZ)             // 8448 -> L at byte 33792 (inside buf area)

__device__ uint4 g_wh4[NEXP * DMODEL / 8];   // W hi, bf16 row-major
__device__ uint4 g_wl4[NEXP * DMODEL / 8];   // W lo

#define MMAB(c, a, b0, b1) asm volatile(                                  \
    "mma.sync.aligned.m16n8k16.row.col.f32.bf16.bf16.f32 "                \
    "{%0,%1,%2,%3}, {%4,%5,%6,%7}, {%8,%9}, {%0,%1,%2,%3};"               \
    : "+f"((c)[0]), "+f"((c)[1]), "+f"((c)[2]), "+f"((c)[3])              \
    : "r"((a)[0]), "r"((a)[1]), "r"((a)[2]), "r"((a)[3]),                 \
      "r"(b0), "r"(b1))

#define LDM4(r, addr) asm volatile(                                       \
    "ldmatrix.sync.aligned.m8n8.x4.shared.b16 {%0,%1,%2,%3}, [%4];"       \
    : "=r"((r)[0]), "=r"((r)[1]), "=r"((r)[2]), "=r"((r)[3]) : "r"(addr))

#define STS64(addr, u0, u1) asm volatile(                                 \
    "st.shared.v2.u32 [%0], {%1,%2};" :: "r"(addr), "r"(u0), "r"(u1) : "memory")

#define CPA16(saddr, gptr) asm volatile(                                  \
    "cp.async.cg.shared.global [%0], [%1], 16;" :: "r"(saddr), "l"(gptr) : "memory")

static __device__ __forceinline__ void bsplit(float4 v, uint32_t& h0, uint32_t& h1,
                                              uint32_t& l0, uint32_t& l1) {
    asm("cvt.rn.bf16x2.f32 %0, %1, %2;" : "=r"(h0) : "f"(v.y), "f"(v.x));
    asm("cvt.rn.bf16x2.f32 %0, %1, %2;" : "=r"(h1) : "f"(v.w), "f"(v.z));
    float f0 = __uint_as_float(h0 << 16);
    float f1 = __uint_as_float(h0 & 0xffff0000u);
    float f2 = __uint_as_float(h1 << 16);
    float f3 = __uint_as_float(h1 & 0xffff0000u);
    asm("cvt.rn.bf16x2.f32 %0, %1, %2;" : "=r"(l0) : "f"(v.y - f1), "f"(v.x - f0));
    asm("cvt.rn.bf16x2.f32 %0, %1, %2;" : "=r"(l1) : "f"(v.w - f3), "f"(v.z - f2));
}

__global__ void wsplit_kernel(const float* __restrict__ Wg) {
    const int i = blockIdx.x * 256 + threadIdx.x;
    const float4* w4 = (const float4*)Wg;
    float4 a = w4[2 * i], b = w4[2 * i + 1];
    uint4 h, l;
    bsplit(a, h.x, h.y, l.x, l.y);
    bsplit(b, h.z, h.w, l.z, l.w);
    g_wh4[i] = h;
    g_wl4[i] = l;
}

__global__ __launch_bounds__(NTHREADS, 2)
void router_mma_kernel(const float* __restrict__ x, const float* __restrict__ Wg,
                       float* __restrict__ w_out, float* __restrict__ i_out,
                       float* __restrict__ l_out)
{
    extern __shared__ __align__(16) char smc[];
    float* sm = (float*)smc;
    uint32_t sb;
    asm("{ .reg .u64 t; cvta.to.shared.u64 t, %1; cvt.u32.u64 %0, t; }" : "=r"(sb) : "l"(smc));

    const int tid = threadIdx.x;
    const int wid = tid >> 5;
    const int lid = tid & 31;
    const int g   = lid >> 2;
    const int t   = lid & 3;
    const int wm  = wid >> 2;          // 0..1 : 32-token slab
    const int wn  = (wid >> 1) & 1;    // 0..1 : 32-expert slab
    const int wk  = wid & 1;           // k16 sub-slices {wk, wk+2}
    const int t0  = blockIdx.x * BM;

    float c[2][4][4];                  // 32 accumulator regs
    #pragma unroll
    for (int i = 0; i < 2; i++)
        #pragma unroll
        for (int j = 0; j < 4; j++)
            #pragma unroll
            for (int k = 0; k < 4; k++) c[i][j][k] = 0.0f;

    const float4* xg = (const float4*)(x + (size_t)t0 * DMODEL);

    // prologue: x(0) prefetch + W(0) cp.async
    float4 xr[4];
    #pragma unroll
    for (int p = 0; p < 4; p++) {
        int id = tid + 256 * p;                          // 1024 float4/chunk
        xr[p] = xg[(size_t)(id >> 4) * (DMODEL / 4) + (id & 15)];
    }
    {
        #pragma unroll
        for (int p = 0; p < 2; p++) {
            int id = tid + 256 * p;                      // 512 uint4/tile
            int e = id >> 3, q = id & 7;
            uint32_t ad = (uint32_t)e * P2 + (uint32_t)q * 16;
            CPA16(sb + WH_T + ad, (const char*)&g_wh4[e * (DMODEL / 8) + q]);
            CPA16(sb + WL_T + ad, (const char*)&g_wl4[e * (DMODEL / 8) + q]);
        }
        asm volatile("cp.async.commit_group;" ::: "memory");
    }

    const uint32_t a_base = (uint32_t)(wm * 32 + (lid & 15)) * P2 + (lid >> 4) * 16;
    const uint32_t b_base = (uint32_t)(wn * 32 + (lid & 7) + ((lid >> 4) & 1) * 8) * P2
                          + ((lid >> 3) & 1) * 16;

    #pragma unroll 1
    for (int ck = 0; ck < NCHUNK; ck++) {
        const uint32_t bo = sb + (ck & 1) * SBUF;

        // ---- x split + stage ----
        #pragma unroll
        for (int p = 0; p < 4; p++) {
            int id = tid + 256 * p;
            uint32_t ad = (uint32_t)(id >> 4) * P2 + (uint32_t)(id & 15) * 8;
            uint32_t h0, h1, l0, l1;
            bsplit(xr[p], h0, h1, l0, l1);
            STS64(bo + XH_T + ad, h0, h1);
            STS64(bo + XL_T + ad, l0, l1);
        }
        asm volatile("cp.async.wait_group 0;" ::: "memory");
        __syncthreads();

        // ---- W(ck+1) cp.async + x(ck+1) prefetch (overlap MMAs) ----
        if (ck + 1 < NCHUNK) {
            const uint32_t bn = sb + ((ck + 1) & 1) * SBUF;
            #pragma unroll
            for (int p = 0; p < 2; p++) {
                int id = tid + 256 * p;
                int e = id >> 3, q = id & 7;
                uint32_t ad = (uint32_t)e * P2 + (uint32_t)q * 16;
                int gi = e * (DMODEL / 8) + (ck + 1) * 8 + q;
                CPA16(bn + WH_T + ad, (const char*)&g_wh4[gi]);
                CPA16(bn + WL_T + ad, (const char*)&g_wl4[gi]);
            }
            asm volatile("cp.async.commit_group;" ::: "memory");

            const int kq = (ck + 1) * (KC / 4);
            #pragma unroll
            for (int p = 0; p < 4; p++) {
                int id = tid + 256 * p;
                xr[p] = xg[(size_t)(id >> 4) * (DMODEL / 4) + kq + (id & 15)];
            }
        }

        // ---- 2 k16-slices for this warp: slices {wk, wk+2} ----
        #pragma unroll
        for (int ss = 0; ss < 2; ss++) {
            const uint32_t so = (uint32_t)(wk + 2 * ss) * 32;
            uint32_t ah[2][4], al[2][4], bh[2][4], bl[2][4];
            #pragma unroll
            for (int mt = 0; mt < 2; mt++) {
                uint32_t aa = bo + XH_T + a_base + mt * 16 * P2 + so;
                LDM4(ah[mt], aa);
                LDM4(al[mt], aa + TILE2);
            }
            #pragma unroll
            for (int bp = 0; bp < 2; bp++) {
                uint32_t ba = bo + WH_T + b_base + bp * 16 * P2 + so;
                LDM4(bh[bp], ba);
                LDM4(bl[bp], ba + TILE2);
            }
            // pass-major: hh, hl, lh
            #pragma unroll
            for (int mt = 0; mt < 2; mt++)
                #pragma unroll
                for (int nt = 0; nt < 4; nt++)
                    MMAB(c[mt][nt], ah[mt], bh[nt >> 1][2*(nt & 1)], bh[nt >> 1][2*(nt & 1) + 1]);
            #pragma unroll
            for (int mt = 0; mt < 2; mt++)
                #pragma unroll
                for (int nt = 0; nt < 4; nt++)
                    MMAB(c[mt][nt], ah[mt], bl[nt >> 1][2*(nt & 1)], bl[nt >> 1][2*(nt & 1) + 1]);
            #pragma unroll
            for (int mt = 0; mt < 2; mt++)
                #pragma unroll
                for (int nt = 0; nt < 4; nt++)
                    MMAB(c[mt][nt], al[mt], bh[nt >> 1][2*(nt & 1)], bh[nt >> 1][2*(nt & 1) + 1]);
        }
    }
    __syncthreads();

    // ---- epilogue: 8 partial 32x32 tiles (pitch 33) ----
    {
        float* Pw = sm + wid * PSZ;
        #pragma unroll
        for (int mt = 0; mt < 2; mt++) {
            const int row = 16 * mt + g;
            #pragma unroll
            for (int nt = 0; nt < 4; nt++) {
                const int col = 8 * nt + 2 * t;
                Pw[row * PPITCH + col]           = c[mt][nt][0];
                Pw[row * PPITCH + col + 1]       = c[mt][nt][1];
                Pw[(row + 8) * PPITCH + col]     = c[mt][nt][2];
                Pw[(row + 8) * PPITCH + col + 1] = c[mt][nt][3];
            }
        }
    }
    __syncthreads();

    // ---- reduce wk pairs into L[64][65] ----
    float* L = sm + L_OFF;
    #pragma unroll
    for (int j = 0; j < 16; j++) {
        int idx = tid + 256 * j;                  // 4096 elements
        int row = idx >> 6, col = idx & 63;
        int base = ((row >> 5) * 4 + (col >> 5) * 2) * PSZ + (row & 31) * PPITCH + (col & 31);
        L[row * LPITCH + col] = sm[base] + sm[base + PSZ];
    }
    __syncthreads();

    // ---- per-token top-4 + near-tie fp64 rescue + softmax (warps 0,1) ----
    if (tid < BM) {
        const float* row = &L[tid * LPITCH];
        float v1 = -INFINITY, v2 = -INFINITY, v3 = -INFINITY, v4 = -INFINITY;
        int   i1 = 0, i2 = 0, i3 = 0, i4 = 0;
        #pragma unroll 8
        for (int e = 0; e < NEXP; e++) {
            float v = row[e];
            if (v > v1)      { v4=v3;i4=i3; v3=v2;i3=i2; v2=v1;i2=i1; v1=v;i1=e; }
            else if (v > v2) { v4=v3;i4=i3; v3=v2;i3=i2; v2=v;i2=e; }
            else if (v > v3) { v4=v3;i4=i3; v3=v;i3=e; }
            else if (v > v4) { v4=v;i4=e; }
        }

        const bool flagged = (v1 - v2 < THR) || (v2 - v3 < THR);
        unsigned m = __ballot_sync(0xffffffffu, flagged);
        while (m) {
            const int src = __ffs(m) - 1;
            m &= m - 1;
            const int tok = t0 + (tid & ~31) + src;
            int cand[4];
            cand[0] = __shfl_sync(0xffffffffu, i1, src);
            cand[1] = __shfl_sync(0xffffffffu, i2, src);
            cand[2] = __shfl_sync(0xffffffffu, i3, src);
            cand[3] = __shfl_sync(0xffffffffu, i4, src);

            const int slot = lid >> 3;
            const int kl   = lid & 7;
            const int e    = cand[slot];
            const float* xp = x  + (size_t)tok * DMODEL;
            const float* wp = Wg + (size_t)e   * DMODEL;

            double a0 = 0.0, a1 = 0.0, a2 = 0.0, a3 = 0.0;
            #pragma unroll 4
            for (int jj = 0; jj < 256; jj += 4) {
                int k0 = (jj + 0) * 8 + kl;
                int k1 = (jj + 1) * 8 + kl;
                int k2 = (jj + 2) * 8 + kl;
                int k3 = (jj + 3) * 8 + kl;
                a0 = fma((double)xp[k0], (double)wp[k0], a0);
                a1 = fma((double)xp[k1], (double)wp[k1], a1);
                a2 = fma((double)xp[k2], (double)wp[k2], a2);
                a3 = fma((double)xp[k3], (double)wp[k3], a3);
            }
            double tot = (a0 + a1) + (a2 + a3);
            tot += __shfl_xor_sync(0xffffffffu, tot, 4);
            tot += __shfl_xor_sync(0xffffffffu, tot, 2);
            tot += __shfl_xor_sync(0xffffffffu, tot, 1);

            double gv[4];
            gv[0] = __shfl_sync(0xffffffffu, tot, 0);
            gv[1] = __shfl_sync(0xffffffffu, tot, 8);
            gv[2] = __shfl_sync(0xffffffffu, tot, 16);
            gv[3] = __shfl_sync(0xffffffffu, tot, 24);

            if (lid == src) {
                int o1 = 0;
                #pragma unroll
                for (int s2 = 1; s2 < 4; s2++)
                    if (gv[s2] > gv[o1] || (gv[s2] == gv[o1] && cand[s2] < cand[o1])) o1 = s2;
                int o2 = (o1 == 0) ? 1 : 0;
                #pragma unroll
                for (int s2 = 0; s2 < 4; s2++) {
                    if (s2 == o1 || s2 == o2) continue;
                    if (gv[s2] > gv[o2] || (gv[s2] == gv[o2] && cand[s2] < cand[o2])) o2 = s2;
                }
                i1 = cand[o1]; i2 = cand[o2];
                v1 = row[i1];  v2 = row[i2];
            }
        }

        float S = 0.0f;
        #pragma unroll 8
        for (int e = 0; e < NEXP; e++) S += expf(row[e] - v1);
        const float p1  = expf(row[i1] - v1) / S;
        const float p2  = expf(v2 - v1) / S;
        const float inv = 1.0f / (p1 + p2 + 1e-10f);
        const size_t n = (size_t)(t0 + tid);
        w_out[2 * n]     = p1 * inv;
        w_out[2 * n + 1] = p2 * inv;
        i_out[2 * n]     = (float)i1;
        i_out[2 * n + 1] = (float)i2;
    }

    // coalesced logits store: 1024 float4 / 256 threads = 4 each
    #pragma unroll
    for (int p = 0; p < 4; p++) {
        int id = tid + 256 * p;
        int rr = id >> 4, q = id & 15;
        float4 v;
        v.x = L[rr * LPITCH + 4 * q];
        v.y = L[rr * LPITCH + 4 * q + 1];
        v.z = L[rr * LPITCH + 4 * q + 2];
        v.w = L[rr * LPITCH + 4 * q + 3];
        *(float4*)(l_out + (size_t)(t0 + rr) * NEXP + 4 * q) = v;
    }
}

extern "C" void kernel_launch(void* const* d_in, const int* in_sizes, int n_in,
                              void* d_out, int out_size)
{
    const float* x  = (const float*)d_in[0];
    const float* Wg = (const float*)d_in[1];
    const int N = in_sizes[0] / DMODEL;       // 16384

    float* out   = (float*)d_out;
    float* w_out = out;
    float* i_out = out + (size_t)N * 2;
    float* l_out = out + (size_t)N * 4;

    wsplit_kernel<<<NEXP * DMODEL / 8 / 256, 256>>>(Wg);

    cudaFuncSetAttribute(router_mma_kernel,
                         cudaFuncAttributeMaxDynamicSharedMemorySize, SMEM_BYTES);
    router_mma_kernel<<<N / BM, NTHREADS, SMEM_BYTES>>>(x, Wg, w_out, i_out, l_out);
}